// round 3
// baseline (speedup 1.0000x reference)
#include <cuda_runtime.h>

// Constants from the reference
#define EPS     1e-10f
#define B_CONST (1.0f + 0.1f + 0.05f)   // 1.15
#define BR      (1.0f + 0.1f - 0.05f)   // 1.05
#define HW      (512 * 512)

// Packed table: .x = v, .y = 1/(v+EPS). One 8B gather returns both values.
__device__ float2 g_vv[HW];

// Vectorized table build: 4 pixels per thread, float4 loads/stores.
__global__ void __launch_bounds__(256) build_v_kernel(const float4* __restrict__ vin4,
                                                      float* __restrict__ out) {
    int t = blockIdx.x * blockDim.x + threadIdx.x;
    if (t < HW / 4) {
        float4 a = vin4[t];
        float4 b = vin4[t + HW / 4];
        float4 c = vin4[t + 2 * (HW / 4)];
        float4* dst = reinterpret_cast<float4*>(g_vv);  // (v,inv,v,inv) pairs

        float v0 = ((a.x + b.x + c.x) * (1.0f/3.0f) * 255.0f + 1.0f) * (1.0f/256.0f);
        float v1 = ((a.y + b.y + c.y) * (1.0f/3.0f) * 255.0f + 1.0f) * (1.0f/256.0f);
        float v2 = ((a.z + b.z + c.z) * (1.0f/3.0f) * 255.0f + 1.0f) * (1.0f/256.0f);
        float v3 = ((a.w + b.w + c.w) * (1.0f/3.0f) * 255.0f + 1.0f) * (1.0f/256.0f);

        dst[2 * t + 0] = make_float4(v0, __frcp_rn(v0 + EPS), v1, __frcp_rn(v1 + EPS));
        dst[2 * t + 1] = make_float4(v2, __frcp_rn(v2 + EPS), v3, __frcp_rn(v3 + EPS));
    }
    if (t == 0) out[0] = 0.0f;
}

__global__ void __launch_bounds__(256) whdr_loss_kernel(
    const int4*   __restrict__ coords,    // (N,4) int32: x1,y1,x2,y2
    const int4*   __restrict__ darker4,   // (N,) viewed as int4
    const float4* __restrict__ weights4,  // (N,) viewed as float4
    float* __restrict__ out,
    int n)
{
    const float inv_b = 1.0f / B_CONST;
    const float bl    = 1.0f / BR;
    const float inv_n = 1.0f / (float)n;

    int t    = blockIdx.x * blockDim.x + threadIdx.x;
    int base = t * 4;

    float acc = 0.0f;

    if (base + 3 < n) {
        // Streaming loads (evict-streaming: keep L1 for the gather table)
        int4   d4 = __ldcs(&darker4[t]);
        float4 w4 = __ldcs(&weights4[t]);
        int4 c0 = __ldcs(&coords[base + 0]);
        int4 c1 = __ldcs(&coords[base + 1]);
        int4 c2 = __ldcs(&coords[base + 2]);
        int4 c3 = __ldcs(&coords[base + 3]);

        // Front-batch the 8 independent gathers
        float2 p1[4], p2[4];
        p1[0] = __ldg(&g_vv[(c0.y << 9) | c0.x]);  p2[0] = __ldg(&g_vv[(c0.w << 9) | c0.z]);
        p1[1] = __ldg(&g_vv[(c1.y << 9) | c1.x]);  p2[1] = __ldg(&g_vv[(c1.w << 9) | c1.z]);
        p1[2] = __ldg(&g_vv[(c2.y << 9) | c2.x]);  p2[2] = __ldg(&g_vv[(c2.w << 9) | c2.z]);
        p1[3] = __ldg(&g_vv[(c3.y << 9) | c3.x]);  p2[3] = __ldg(&g_vv[(c3.w << 9) | c3.z]);

        int   dd[4] = {d4.x, d4.y, d4.z, d4.w};
        float ww[4] = {w4.x, w4.y, w4.z, w4.w};

        #pragma unroll
        for (int j = 0; j < 4; j++) {
            float ratio     = p1[j].x * p2[j].y;   // r1 / (r2 + EPS)
            float ratio_inv = p2[j].x * p1[j].y;   // r2 / (r1 + EPS)

            float l1 = (ratio > inv_b)   ? (ratio - inv_b + (B_CONST - ratio_inv)) : 0.0f;
            float l2 = (ratio < B_CONST) ? (B_CONST - ratio + (ratio_inv - inv_b)) : 0.0f;
            float l0 = (ratio > BR) ? (ratio - BR + (bl - ratio_inv))
                     : ((ratio < bl) ? (bl - ratio + (ratio_inv - BR)) : 0.0f);

            float per = (dd[j] == 1) ? l1 : ((dd[j] == 2) ? l2 : l0);
            acc += ww[j] * per;
        }
    } else if (base < n) {
        // Scalar tail (n not multiple of 4)
        const int*   darker  = (const int*)darker4;
        const float* weights = (const float*)weights4;
        for (int i = base; i < n; i++) {
            int4 c  = __ldcs(&coords[i]);
            float2 q1 = __ldg(&g_vv[(c.y << 9) | c.x]);
            float2 q2 = __ldg(&g_vv[(c.w << 9) | c.z]);
            float ratio     = q1.x * q2.y;
            float ratio_inv = q2.x * q1.y;
            float l1 = (ratio > inv_b)   ? (ratio - inv_b + (B_CONST - ratio_inv)) : 0.0f;
            float l2 = (ratio < B_CONST) ? (B_CONST - ratio + (ratio_inv - inv_b)) : 0.0f;
            float l0 = (ratio > BR) ? (ratio - BR + (bl - ratio_inv))
                     : ((ratio < bl) ? (bl - ratio + (ratio_inv - BR)) : 0.0f);
            int d = darker[i];
            acc += weights[i] * ((d == 1) ? l1 : ((d == 2) ? l2 : l0));
        }
    }

    // Warp reduction
    #pragma unroll
    for (int off = 16; off > 0; off >>= 1)
        acc += __shfl_xor_sync(0xffffffffu, acc, off);

    // Block reduction
    __shared__ float warp_sums[8];
    int lane = threadIdx.x & 31;
    int wid  = threadIdx.x >> 5;
    if (lane == 0) warp_sums[wid] = acc;
    __syncthreads();
    if (wid == 0) {
        float s = (lane < (blockDim.x >> 5)) ? warp_sums[lane] : 0.0f;
        #pragma unroll
        for (int off = 4; off > 0; off >>= 1)
            s += __shfl_xor_sync(0xffffffffu, s, off);
        if (lane == 0)
            atomicAdd(out, s * inv_n);
    }
}

extern "C" void kernel_launch(void* const* d_in, const int* in_sizes, int n_in,
                              void* d_out, int out_size)
{
    const float4* vin4    = (const float4*)d_in[0];
    const int4*   coords  = (const int4*)d_in[1];
    const int4*   darker4 = (const int4*)d_in[2];
    const float4* weights4= (const float4*)d_in[3];
    float*        out     = (float*)d_out;

    int n = in_sizes[2];  // darker element count == N

    build_v_kernel<<<(HW / 4 + 255) / 256, 256>>>(vin4, out);

    int threads = 256;
    int elems_per_block = threads * 4;
    int blocks = (n + elems_per_block - 1) / elems_per_block;
    whdr_loss_kernel<<<blocks, threads>>>(coords, darker4, weights4, out, n);
}